// round 13
// baseline (speedup 1.0000x reference)
#include <cuda_runtime.h>
#include <cstdint>

#define BB 8
#define CC 32
#define NN 4096
#define TM 64
#define KN 32
#define NCHUNK (NN / KN)   // 128
#define NTH 128

// packed per-node exp(mean), exp(-mean)
__device__ float2 g_EI[BB * NN];

// ---------------- Kernel 1: channel means -> (E, iE) -------------------------
__global__ void prep_kernel(const float* __restrict__ x) {
    int idx = blockIdx.x * blockDim.x + threadIdx.x;   // over B*N
    if (idx >= BB * NN) return;
    int b = idx / NN;
    int n = idx - b * NN;
    const float* p = x + (size_t)b * CC * NN + n;
    float s = 0.f;
#pragma unroll
    for (int c = 0; c < CC; c++) s += p[(size_t)c * NN];
    s *= (1.0f / CC);
    g_EI[idx] = make_float2(__expf(s), __expf(-s));
}

__device__ __forceinline__ uint32_t f2tf(float f) {
    uint32_t u;
    asm("cvt.rna.tf32.f32 %0, %1;" : "=r"(u) : "f"(f));
    return u;
}
__device__ __forceinline__ float f2tff(float f) { return __uint_as_float(f2tf(f)); }

// ---------------- Kernel 2: SMEM-staged mma.sync tf32 fused GCN --------------
// D[m, c] = sum_n Ag[m,n] * fea[c,n],  Ag[m,n] = adj[m][n] * 2/(1+exp(|cm-cn|))
// (adj symmetric in this problem; sf exactly symmetric — validated R5/R10/R11)
// TM=64: 512 CTAs of 128 threads; warp w owns m-rows [16w, 16w+16).
__global__ __launch_bounds__(NTH) void gcn_mma_kernel(
    const float* __restrict__ x, const float* __restrict__ para,
    const float* __restrict__ adj, float* __restrict__ out)
{
    // Ag tile [64 m][32 n], XOR-swizzled: word = m*32 + ((n&~3)^((m&7)<<2)) + (n&3)
    __shared__ float sA[TM * KN];        // 8 KB
    // fea fragments: [nt(4)][ks(4)][lane(32)] float2 = (fea[c][k], fea[c][k+4])
    __shared__ float2 sB[512];           // 4 KB

    const int b    = blockIdx.y;
    const int m0   = blockIdx.x * TM;
    const int t    = threadIdx.x;
    const int w    = t >> 5;
    const int lane = t & 31;
    const int gr   = lane >> 2;
    const int tc   = lane & 3;

    const float*  fea = x + (size_t)b * CC * NN;
    const float2* EIb = g_EI + b * NN;

    // --- construction role: thread owns rows m = r*16 + cr (r=0..3), col quad n4 ---
    const int cr = t >> 3;     // 0..15
    const int n4 = t & 7;      // 0..7
    // --- B staging role: thread owns channel sc, kstep sks ---
    const int sc  = t >> 2;    // 0..31
    const int sks = t & 3;     // 0..3

    // per-thread m-row exp pairs, invariant over chunks
    float2 Em[4];
#pragma unroll
    for (int r = 0; r < 4; r++) Em[r] = EIb[m0 + r * 16 + cr];

    const float* adjbase = adj + (size_t)(m0 + cr) * NN + n4 * 4;
    const float* feab    = fea + (size_t)sc * NN + sks * 8;

    // prefetch chunk 0
    float4 pfa[4];
#pragma unroll
    for (int r = 0; r < 4; r++)
        pfa[r] = *(const float4*)(adjbase + (size_t)r * 16 * NN);
    float4 pfe0, pfe1;   // (E,iE) for n = n4*4 .. n4*4+3
    {
        const float4* ep = (const float4*)(EIb + n4 * 4);
        pfe0 = ep[0]; pfe1 = ep[1];
    }
    float4 pff0 = *(const float4*)(feab);
    float4 pff1 = *(const float4*)(feab + 4);

    float acc[4][4];
#pragma unroll
    for (int nt = 0; nt < 4; nt++)
#pragma unroll
        for (int i = 0; i < 4; i++) acc[nt][i] = 0.f;

    const int swc   = (cr & 7) << 2;                         // construction swizzle
    const int sbase = ((sc >> 3) * 4 + sks) * 32 + (sc & 7) * 4;

    for (int ch = 0; ch < NCHUNK; ch++) {
        // ---- construct Ag tile into sA (coalesced, swizzled, tf32-rounded) ----
#pragma unroll
        for (int r = 0; r < 4; r++) {
            const float4 a = pfa[r];
            const float E = Em[r].x, I = Em[r].y;
            const float t0 = fmaxf(E * pfe0.y, pfe0.x * I);  // exp(|cm - cn|)
            const float t1 = fmaxf(E * pfe0.w, pfe0.z * I);
            const float t2 = fmaxf(E * pfe1.y, pfe1.x * I);
            const float t3 = fmaxf(E * pfe1.w, pfe1.z * I);
            float4 v;
            v.x = f2tff(__fdividef(a.x + a.x, 1.0f + t0));
            v.y = f2tff(__fdividef(a.y + a.y, 1.0f + t1));
            v.z = f2tff(__fdividef(a.z + a.z, 1.0f + t2));
            v.w = f2tff(__fdividef(a.w + a.w, 1.0f + t3));
            *(float4*)&sA[(r * 16 + cr) * 32 + ((n4 * 4) ^ swc)] = v;
        }
        // ---- stage fea fragments (pre-transposed to mma B layout) ----
        sB[sbase + 0] = make_float2(f2tff(pff0.x), f2tff(pff1.x));
        sB[sbase + 1] = make_float2(f2tff(pff0.y), f2tff(pff1.y));
        sB[sbase + 2] = make_float2(f2tff(pff0.z), f2tff(pff1.z));
        sB[sbase + 3] = make_float2(f2tff(pff0.w), f2tff(pff1.w));
        __syncthreads();

        // ---- prefetch next chunk (lands under the mma section) ----
        if (ch + 1 < NCHUNK) {
            const int n1 = (ch + 1) * KN;
#pragma unroll
            for (int r = 0; r < 4; r++)
                pfa[r] = *(const float4*)(adjbase + (size_t)r * 16 * NN + n1);
            const float4* ep = (const float4*)(EIb + n1 + n4 * 4);
            pfe0 = ep[0]; pfe1 = ep[1];
            pff0 = *(const float4*)(feab + n1);
            pff1 = *(const float4*)(feab + n1 + 4);
        }

        // ---- 16 mma per warp: 4 ksteps x 4 c-tiles ----
        {
            const float* pA = sA + (16 * w + gr) * 32;
            const int swb = gr << 2;
#pragma unroll
            for (int ks = 0; ks < 4; ks++) {
                const uint32_t A0 = __float_as_uint(pA[((ks * 8)     ^ swb) + tc]);
                const uint32_t A1 = __float_as_uint(pA[256 + (((ks * 8)     ^ swb) + tc)]);
                const uint32_t A2 = __float_as_uint(pA[((ks * 8 + 4) ^ swb) + tc]);
                const uint32_t A3 = __float_as_uint(pA[256 + (((ks * 8 + 4) ^ swb) + tc)]);
#pragma unroll
                for (int nt = 0; nt < 4; nt++) {
                    const float2 bb = sB[(nt * 4 + ks) * 32 + lane];
                    const uint32_t B0 = __float_as_uint(bb.x);
                    const uint32_t B1 = __float_as_uint(bb.y);
                    asm volatile(
                        "mma.sync.aligned.m16n8k8.row.col.f32.tf32.tf32.f32 "
                        "{%0,%1,%2,%3}, {%4,%5,%6,%7}, {%8,%9}, {%0,%1,%2,%3};"
                        : "+f"(acc[nt][0]), "+f"(acc[nt][1]),
                          "+f"(acc[nt][2]), "+f"(acc[nt][3])
                        : "r"(A0), "r"(A1), "r"(A2), "r"(A3), "r"(B0), "r"(B1));
                }
            }
        }
        __syncthreads();
    }

    // ---- epilogue: para * acc, relu, direct STG ----
    {
        const int mr0 = m0 + 16 * w + gr;
        const int mr1 = mr0 + 8;
#pragma unroll
        for (int nt = 0; nt < 4; nt++) {
            const int cA = nt * 8 + 2 * tc;
            const int cB = cA + 1;
            out[(size_t)(b * CC + cA) * NN + mr0] = fmaxf(acc[nt][0] * para[cA * NN + mr0], 0.f);
            out[(size_t)(b * CC + cB) * NN + mr0] = fmaxf(acc[nt][1] * para[cB * NN + mr0], 0.f);
            out[(size_t)(b * CC + cA) * NN + mr1] = fmaxf(acc[nt][2] * para[cA * NN + mr1], 0.f);
            out[(size_t)(b * CC + cB) * NN + mr1] = fmaxf(acc[nt][3] * para[cB * NN + mr1], 0.f);
        }
    }
}

extern "C" void kernel_launch(void* const* d_in, const int* in_sizes, int n_in,
                              void* d_out, int out_size) {
    const float* x    = (const float*)d_in[0];  // [8,32,64,64]
    const float* para = (const float*)d_in[1];  // [1,32,64,64]
    const float* adj  = (const float*)d_in[2];  // [4096,4096]
    float* out = (float*)d_out;

    prep_kernel<<<(BB * NN) / 256, 256>>>(x);
    dim3 grid(NN / TM, BB);                     // 64 x 8 = 512 CTAs
    gcn_mma_kernel<<<grid, NTH>>>(x, para, adj, out);
}